// round 14
// baseline (speedup 1.0000x reference)
#include <cuda_runtime.h>
#include <cuda_fp16.h>
#include <math.h>
#include <stdint.h>

#define BATCH 2
#define SEQ   2048
#define DIM   1024
#define NH    16
#define HD    64
#define MTOT  (BATCH*SEQ)   // 4096

// ---------------------------------------------------------------------------
// Scratch (allocation-free rule: __device__ globals)
// ---------------------------------------------------------------------------
__device__ __half g_xh[MTOT*DIM];     // x as fp16
__device__ __half g_ah[MTOT*DIM];     // attention output, fp16
__device__ __half g_qh[MTOT*DIM];     // Q, prescaled, fp16
__device__ __half g_khi[MTOT*DIM];    // K fp16 hi
__device__ __half g_klo[MTOT*DIM];    // K fp16 lo
__device__ __half g_vt[MTOT*DIM];     // V fp16, transposed: [b,h][d][s]
// Transposed weights as fp16: WT[n][k] = fp16(W[k][n])
__device__ __half g_wqt[DIM*DIM];
__device__ __half g_wkt[DIM*DIM];
__device__ __half g_wvt[DIM*DIM];
__device__ __half g_wot[DIM*DIM];

struct Ptr4 { const float* W[4]; __half* WT[4]; };

// ---------------------------------------------------------------------------
// Helpers
// ---------------------------------------------------------------------------
__device__ __forceinline__ uint32_t h2bits(__half2 h) {
    return *reinterpret_cast<uint32_t*>(&h);
}
__device__ __forceinline__ uint32_t smem_u32(const void* p) {
    uint32_t a;
    asm("{ .reg .u64 t; cvta.to.shared.u64 t, %1; cvt.u32.u64 %0, t; }"
        : "=r"(a) : "l"(p));
    return a;
}

#define MMA_F16(d, a, b0, b1) \
    asm volatile("mma.sync.aligned.m16n8k16.row.col.f32.f16.f16.f32 " \
        "{%0,%1,%2,%3}, {%4,%5,%6,%7}, {%8,%9}, {%0,%1,%2,%3};" \
        : "+f"((d)[0]), "+f"((d)[1]), "+f"((d)[2]), "+f"((d)[3]) \
        : "r"((a)[0]), "r"((a)[1]), "r"((a)[2]), "r"((a)[3]), \
          "r"(b0), "r"(b1))

#define LDSM_X4(r0, r1, r2, r3, addr) \
    asm volatile("ldmatrix.sync.aligned.m8n8.x4.shared.b16 {%0,%1,%2,%3}, [%4];" \
        : "=r"(r0), "=r"(r1), "=r"(r2), "=r"(r3) : "r"(addr))

#define CP_ASYNC16(dst_u32, src_ptr) \
    asm volatile("cp.async.cg.shared.global [%0], [%1], 16;" \
        :: "r"(dst_u32), "l"(src_ptr))
#define CP_COMMIT() asm volatile("cp.async.commit_group;" ::: "memory")
#define CP_WAIT0()  asm volatile("cp.async.wait_group 0;"  ::: "memory")
#define CP_WAIT1()  asm volatile("cp.async.wait_group 1;"  ::: "memory")

// ---------------------------------------------------------------------------
// x fp32 -> fp16 (one shot)
// ---------------------------------------------------------------------------
__global__ __launch_bounds__(256) void f32_to_f16_kernel(
    const float* __restrict__ src, __half* __restrict__ dst, int n4)
{
    int i = blockIdx.x * blockDim.x + threadIdx.x;
    int stride = gridDim.x * blockDim.x;
    for (; i < n4; i += stride) {
        float4 v = reinterpret_cast<const float4*>(src)[i];
        uint2 w;
        w.x = h2bits(__floats2half2_rn(v.x, v.y));
        w.y = h2bits(__floats2half2_rn(v.z, v.w));
        reinterpret_cast<uint2*>(dst)[i] = w;
    }
}

// ---------------------------------------------------------------------------
// Fused transpose + fp16-convert: all 4 weights in one launch (z selects)
// ---------------------------------------------------------------------------
__global__ __launch_bounds__(256) void transpose_f16_kernel(Ptr4 p)
{
    __shared__ float tile[32][33];
    const float* W  = p.W[blockIdx.z];
    __half*      WT = p.WT[blockIdx.z];
    const int k0 = blockIdx.y * 32;
    const int n0 = blockIdx.x * 32;
    const int tx = threadIdx.x;
    const int ty = threadIdx.y;
    #pragma unroll
    for (int i = ty; i < 32; i += 8)
        tile[i][tx] = W[(size_t)(k0 + i) * DIM + n0 + tx];
    __syncthreads();
    #pragma unroll
    for (int i = ty; i < 32; i += 8)
        WT[(size_t)(n0 + i) * DIM + k0 + tx] = __float2half_rn(tile[tx][i]);
}

// ---------------------------------------------------------------------------
// fp16 GEMM v4: CTA tile 256x128, 8 warps (4M x 2N, 64x64 each), BK=32,
// cp.async 2-stage, ldmatrix.x4 fragment loads (8 LDSM/kt vs 48 LDS.32).
// Grid = (DIM/128, MTOT/256) = 128 CTAs = ONE wave.
// Smem stride 20 words -> LDSM phases hit distinct banks (20*r mod 32).
// Epilogue modes: 0: Cf=v+bias | 1: Ch=fp16(v/8) | 2: Ch/Cl=fp16 hi/lo
//                 3: Ch=fp16(v) transposed to [b,h][d][s]
// ---------------------------------------------------------------------------
#define GSTR    20
#define GSTAGE_A (256*GSTR)        // A words per stage
#define GSTAGE_B (128*GSTR)        // B words per stage
#define GBUF     (GSTAGE_A + GSTAGE_B)
#define GEMM_SMEM (2*GBUF*4)       // 61440 B

__global__ __launch_bounds__(256, 1) void gemm_f16_kernel(
    const __half* __restrict__ Ah, const __half* __restrict__ BT,
    float* __restrict__ Cf, __half* __restrict__ Ch, __half* __restrict__ Cl,
    const float* __restrict__ bias, int mode)
{
    extern __shared__ uint32_t smw[];
    const int tid  = threadIdx.x;
    const int lane = tid & 31;
    const int wid  = tid >> 5;        // 0..7
    const int wm   = wid & 3;         // 4 warps in M
    const int wn   = wid >> 2;        // 2 warps in N
    const int gid  = lane >> 2;
    const int tig  = lane & 3;
    const int bx   = blockIdx.x;
    const int by   = blockIdx.y;

    const int lrow = tid >> 2;        // 0..63
    const int lseg = tid & 3;         // 16B segment (8 halves)

    const __half* Ag = Ah + (size_t)(by * 256) * DIM;
    const __half* Bg = BT + (size_t)(bx * 128) * DIM;
    const uint32_t sbase = smem_u32(smw);

    // ldmatrix per-lane base offsets (bytes): lanes 0-15 -> rows (l&15),
    // lanes 16-31 -> same rows + 16B (k words +4).
    const uint32_t lm_a = (uint32_t)(((wm * 64 + (lane & 15)) * GSTR + (lane >> 4) * 4) * 4);
    const uint32_t lm_b = (uint32_t)(((GSTAGE_B ? 0 : 0) + (wn * 64 + (lane & 15)) * GSTR + (lane >> 4) * 4) * 4)
                          + (uint32_t)(GSTAGE_A * 4);

    auto prefetch = [&](int s) {
        const uint32_t base = sbase + (uint32_t)(s & 1) * (GBUF * 4);
        const int kof = s * 32 + lseg * 8;
        #pragma unroll
        for (int i = 0; i < 4; i++) {           // A: 256 rows
            const int row = lrow + i * 64;
            CP_ASYNC16(base + (uint32_t)((row * GSTR + lseg * 4) * 4),
                       Ag + (size_t)row * DIM + kof);
        }
        #pragma unroll
        for (int i = 0; i < 2; i++) {           // B: 128 rows
            const int row = lrow + i * 64;
            CP_ASYNC16(base + (uint32_t)((GSTAGE_A + row * GSTR + lseg * 4) * 4),
                       Bg + (size_t)row * DIM + kof);
        }
        CP_COMMIT();
    };

    float c[4][8][4];
    #pragma unroll
    for (int i = 0; i < 4; i++)
        #pragma unroll
        for (int j = 0; j < 8; j++)
            #pragma unroll
            for (int k = 0; k < 4; k++)
                c[i][j][k] = 0.0f;

    prefetch(0);
    prefetch(1);

    const int NS = DIM / 32;
    for (int s = 0; s < NS; s++) {
        if (s + 1 < NS) { CP_WAIT1(); } else { CP_WAIT0(); }
        __syncthreads();

        const uint32_t stage = sbase + (uint32_t)(s & 1) * (GBUF * 4);

        #pragma unroll
        for (int kt = 0; kt < 2; kt++) {
            uint32_t af[4][4], bf[8][2];
            const uint32_t ka = stage + lm_a + kt * 32;
            const uint32_t kb = stage + lm_b + kt * 32;
            #pragma unroll
            for (int am = 0; am < 4; am++)
                LDSM_X4(af[am][0], af[am][1], af[am][2], af[am][3],
                        ka + (uint32_t)(am * 16 * GSTR * 4));
            #pragma unroll
            for (int bp = 0; bp < 4; bp++)
                LDSM_X4(bf[2*bp][0], bf[2*bp+1][0], bf[2*bp][1], bf[2*bp+1][1],
                        kb + (uint32_t)(bp * 16 * GSTR * 4));
            #pragma unroll
            for (int am = 0; am < 4; am++)
                #pragma unroll
                for (int bn = 0; bn < 8; bn++)
                    MMA_F16(c[am][bn], af[am], bf[bn][0], bf[bn][1]);
        }

        __syncthreads();
        if (s + 2 < NS) prefetch(s + 2);
    }

    const int rbase = by * 256 + wm * 64 + gid;
    const int cbase = bx * 128 + wn * 64 + tig * 2;
    #pragma unroll
    for (int am = 0; am < 4; am++) {
        #pragma unroll
        for (int bn = 0; bn < 8; bn++) {
            const int col = cbase + bn * 8;
            const int r0  = rbase + am * 16;
            const float v00 = c[am][bn][0], v01 = c[am][bn][1];
            const float v10 = c[am][bn][2], v11 = c[am][bn][3];
            if (mode == 0) {
                float b0 = bias[col], b1 = bias[col + 1];
                *reinterpret_cast<float2*>(Cf + (size_t)r0 * DIM + col) =
                    make_float2(v00 + b0, v01 + b1);
                *reinterpret_cast<float2*>(Cf + (size_t)(r0 + 8) * DIM + col) =
                    make_float2(v10 + b0, v11 + b1);
            } else if (mode == 1) {
                reinterpret_cast<uint32_t*>(Ch)[((size_t)r0 * DIM + col) >> 1] =
                    h2bits(__floats2half2_rn(v00 * 0.125f, v01 * 0.125f));
                reinterpret_cast<uint32_t*>(Ch)[((size_t)(r0 + 8) * DIM + col) >> 1] =
                    h2bits(__floats2half2_rn(v10 * 0.125f, v11 * 0.125f));
            } else if (mode == 2) {
                __half2 h0 = __floats2half2_rn(v00, v01);
                __half2 h1 = __floats2half2_rn(v10, v11);
                float2 f0 = __half22float2(h0), f1 = __half22float2(h1);
                reinterpret_cast<uint32_t*>(Ch)[((size_t)r0 * DIM + col) >> 1] = h2bits(h0);
                reinterpret_cast<uint32_t*>(Ch)[((size_t)(r0 + 8) * DIM + col) >> 1] = h2bits(h1);
                reinterpret_cast<uint32_t*>(Cl)[((size_t)r0 * DIM + col) >> 1] =
                    h2bits(__floats2half2_rn(v00 - f0.x, v01 - f0.y));
                reinterpret_cast<uint32_t*>(Cl)[((size_t)(r0 + 8) * DIM + col) >> 1] =
                    h2bits(__floats2half2_rn(v10 - f1.x, v11 - f1.y));
            } else {
                const size_t bb = (size_t)(r0 >> 11) * 2097152;
                const int s0 = r0 & 2047;
                Ch[bb + (size_t)col * 2048 + s0]           = __float2half_rn(v00);
                Ch[bb + (size_t)(col + 1) * 2048 + s0]     = __float2half_rn(v01);
                Ch[bb + (size_t)col * 2048 + s0 + 8]       = __float2half_rn(v10);
                Ch[bb + (size_t)(col + 1) * 2048 + s0 + 8] = __float2half_rn(v11);
            }
        }
    }
}

// ---------------------------------------------------------------------------
// Tensor-core flash attention (R11 proven, fp16 output) — unchanged.
// 2-term QK (qh*khi + qh*klo), fp16 PV, pure-copy tiles, 128thr, 64 q rows.
// ---------------------------------------------------------------------------
#define ATTN_SMEM (4*64*36*4)    // 36864 B

__global__ __launch_bounds__(128, 4) void attn_tc_kernel(
    const __half* __restrict__ Qh, const __half* __restrict__ Khi,
    const __half* __restrict__ Klo, const __half* __restrict__ Vt,
    __half* __restrict__ Oout)
{
    extern __shared__ uint32_t smw[];
    uint32_t* PpW  = smw;
    uint32_t* KhiU = smw + 64 * 36;
    uint32_t* KloU = KhiU + 64 * 36;
    uint32_t* VpW  = KloU + 64 * 36;

    const int b    = blockIdx.z;
    const int h    = blockIdx.y;
    const int q0   = (gridDim.x - 1 - blockIdx.x) * 64;
    const int tid  = threadIdx.x;
    const int wq   = tid >> 5;
    const int lane = tid & 31;
    const int gid  = lane >> 2;
    const int tig  = lane & 3;

    const __half* Qg  = Qh  + ((size_t)b * SEQ + q0) * DIM + h * HD;
    const __half* Khg = Khi + (size_t)b * SEQ * DIM + h * HD;
    const __half* Klg = Klo + (size_t)b * SEQ * DIM + h * HD;
    const __half* Vtg = Vt  + (size_t)(b * NH + h) * (HD * SEQ);

    #pragma unroll
    for (int i = 0; i < 4; i++) {
        int idx = tid + i * 128;
        int r = idx >> 3, seg = idx & 7;
        *reinterpret_cast<uint4*>(PpW + r * 36 + seg * 4) =
            *reinterpret_cast<const uint4*>(Qg + (size_t)r * DIM + seg * 8);
    }
    __syncthreads();

    uint32_t qh[4][4];
    {
        const int rr = wq * 16 + gid;
        #pragma unroll
        for (int kt = 0; kt < 4; kt++) {
            qh[kt][0] = PpW[rr * 36 + kt * 8 + tig];
            qh[kt][1] = PpW[(rr + 8) * 36 + kt * 8 + tig];
            qh[kt][2] = PpW[rr * 36 + kt * 8 + 4 + tig];
            qh[kt][3] = PpW[(rr + 8) * 36 + kt * 8 + 4 + tig];
        }
    }

    float m0 = -1e30f, m1 = -1e30f, l0 = 0.0f, l1 = 0.0f;
    float o[8][4];
    #pragma unroll
    for (int nt = 0; nt < 8; nt++)
        #pragma unroll
        for (int e = 0; e < 4; e++) o[nt][e] = 0.0f;

    const int ntiles = (q0 >> 6) + 1;
    for (int t = 0; t < ntiles; t++) {
        const int kv0 = t * 64;
        __syncthreads();
        #pragma unroll
        for (int i = 0; i < 4; i++) {
            int idx = tid + i * 128;
            int r = idx >> 3, seg = idx & 7;
            *reinterpret_cast<uint4*>(KhiU + r * 36 + seg * 4) =
                *reinterpret_cast<const uint4*>(Khg + (size_t)(kv0 + r) * DIM + seg * 8);
            *reinterpret_cast<uint4*>(KloU + r * 36 + seg * 4) =
                *reinterpret_cast<const uint4*>(Klg + (size_t)(kv0 + r) * DIM + seg * 8);
            *reinterpret_cast<uint4*>(VpW + r * 36 + seg * 4) =
                *reinterpret_cast<const uint4*>(Vtg + (size_t)r * SEQ + kv0 + seg * 8);
        }
        __syncthreads();

        float s[8][4];
        #pragma unroll
        for (int nt = 0; nt < 8; nt++)
            #pragma unroll
            for (int e = 0; e < 4; e++) s[nt][e] = 0.0f;

        #pragma unroll
        for (int kt = 0; kt < 4; kt++) {
            #pragma unroll
            for (int nt = 0; nt < 8; nt++) {
                const int boff = (nt * 8 + gid) * 36 + kt * 8 + tig;
                uint32_t bh0 = KhiU[boff], bh1 = KhiU[boff + 4];
                uint32_t bl0 = KloU[boff], bl1 = KloU[boff + 4];
                MMA_F16(s[nt], qh[kt], bh0, bh1);
                MMA_F16(s[nt], qh[kt], bl0, bl1);
            }
        }

        const int r0g = q0 + wq * 16 + gid;
        const int r1g = r0g + 8;
        if (kv0 == q0) {
            #pragma unroll
            for (int nt = 0; nt < 8; nt++) {
                const int c0 = kv0 + nt * 8 + 2 * tig;
                if (c0     > r0g) s[nt][0] = -1e30f;
                if (c0 + 1 > r0g) s[nt][1] = -1e30f;
                if (c0     > r1g) s[nt][2] = -1e30f;
                if (c0 + 1 > r1g) s[nt][3] = -1e30f;
            }
        }

        float mx0 = -1e30f, mx1 = -1e30f;
        #pragma unroll
        for (int nt = 0; nt < 8; nt++) {
            mx0 = fmaxf(mx0, fmaxf(s[nt][0], s[nt][1]));
            mx1 = fmaxf(mx1, fmaxf(s[nt][2], s[nt][3]));
        }
        mx0 = fmaxf(mx0, __shfl_xor_sync(0xffffffffu, mx0, 1));
        mx0 = fmaxf(mx0, __shfl_xor_sync(0xffffffffu, mx0, 2));
        mx1 = fmaxf(mx1, __shfl_xor_sync(0xffffffffu, mx1, 1));
        mx1 = fmaxf(mx1, __shfl_xor_sync(0xffffffffu, mx1, 2));

        const float nm0 = fmaxf(m0, mx0);
        const float nm1 = fmaxf(m1, mx1);
        const float sc0 = __expf(m0 - nm0);
        const float sc1 = __expf(m1 - nm1);
        m0 = nm0; m1 = nm1;
        l0 *= sc0; l1 *= sc1;

        float sum0 = 0.0f, sum1 = 0.0f;
        const int prow = wq * 16 + gid;
        #pragma unroll
        for (int nt = 0; nt < 8; nt++) {
            float p00 = __expf(s[nt][0] - m0);
            float p01 = __expf(s[nt][1] - m0);
            float p10 = __expf(s[nt][2] - m1);
            float p11 = __expf(s[nt][3] - m1);
            sum0 += p00 + p01;
            sum1 += p10 + p11;
            PpW[prow * 36 + nt * 4 + tig]       = h2bits(__floats2half2_rn(p00, p01));
            PpW[(prow + 8) * 36 + nt * 4 + tig] = h2bits(__floats2half2_rn(p10, p11));
            o[nt][0] *= sc0; o[nt][1] *= sc0;
            o[nt][2] *= sc1; o[nt][3] *= sc1;
        }
        sum0 += __shfl_xor_sync(0xffffffffu, sum0, 1);
        sum0 += __shfl_xor_sync(0xffffffffu, sum0, 2);
        sum1 += __shfl_xor_sync(0xffffffffu, sum1, 1);
        sum1 += __shfl_xor_sync(0xffffffffu, sum1, 2);
        l0 += sum0; l1 += sum1;

        __syncwarp();

        #pragma unroll
        for (int kt = 0; kt < 4; kt++) {
            uint32_t a[4];
            a[0] = PpW[prow * 36 + kt * 8 + tig];
            a[1] = PpW[(prow + 8) * 36 + kt * 8 + tig];
            a[2] = PpW[prow * 36 + kt * 8 + 4 + tig];
            a[3] = PpW[(prow + 8) * 36 + kt * 8 + 4 + tig];
            #pragma unroll
            for (int nt = 0; nt < 8; nt++) {
                const int voff = (nt * 8 + gid) * 36 + kt * 8 + tig;
                MMA_F16(o[nt], a, VpW[voff], VpW[voff + 4]);
            }
        }
        __syncwarp();
    }

    const float inv0 = 1.0f / l0;
    const float inv1 = 1.0f / l1;
    const int r0g = q0 + wq * 16 + gid;
    uint32_t* OgW = reinterpret_cast<uint32_t*>(
        Oout + (size_t)b * SEQ * DIM + h * HD);
    #pragma unroll
    for (int nt = 0; nt < 8; nt++) {
        const int col = nt * 8 + 2 * tig;
        OgW[((size_t)r0g * DIM + col) >> 1] =
            h2bits(__floats2half2_rn(o[nt][0] * inv0, o[nt][1] * inv0));
        OgW[((size_t)(r0g + 8) * DIM + col) >> 1] =
            h2bits(__floats2half2_rn(o[nt][2] * inv1, o[nt][3] * inv1));
    }
}

// ---------------------------------------------------------------------------
// Launch
// ---------------------------------------------------------------------------
extern "C" void kernel_launch(void* const* d_in, const int* in_sizes, int n_in,
                              void* d_out, int out_size)
{
    const float* x  = (const float*)d_in[0];
    const float* Wq = (const float*)d_in[1];
    const float* Wk = (const float*)d_in[2];
    const float* Wv = (const float*)d_in[3];
    const float* Wo = (const float*)d_in[4];
    const float* bo = (const float*)d_in[5];
    float* out = (float*)d_out;

    __half *xh, *ah, *qh, *khi, *klo, *vt, *wqt, *wkt, *wvt, *wot;
    cudaGetSymbolAddress((void**)&xh,  g_xh);
    cudaGetSymbolAddress((void**)&ah,  g_ah);
    cudaGetSymbolAddress((void**)&qh,  g_qh);
    cudaGetSymbolAddress((void**)&khi, g_khi);
    cudaGetSymbolAddress((void**)&klo, g_klo);
    cudaGetSymbolAddress((void**)&vt,  g_vt);
    cudaGetSymbolAddress((void**)&wqt, g_wqt);
    cudaGetSymbolAddress((void**)&wkt, g_wkt);
    cudaGetSymbolAddress((void**)&wvt, g_wvt);
    cudaGetSymbolAddress((void**)&wot, g_wot);

    cudaFuncSetAttribute(gemm_f16_kernel,
                         cudaFuncAttributeMaxDynamicSharedMemorySize, GEMM_SMEM);
    cudaFuncSetAttribute(attn_tc_kernel,
                         cudaFuncAttributeMaxDynamicSharedMemorySize, ATTN_SMEM);

    // 1) weight transposes (fused) + x -> fp16
    Ptr4 tp;
    tp.W[0] = Wq;   tp.W[1] = Wk;   tp.W[2] = Wv;   tp.W[3] = Wo;
    tp.WT[0] = wqt; tp.WT[1] = wkt; tp.WT[2] = wvt; tp.WT[3] = wot;
    dim3 wt_grid(DIM / 32, DIM / 32, 4);
    dim3 wt_block(32, 8);
    transpose_f16_kernel<<<wt_grid, wt_block>>>(tp);
    f32_to_f16_kernel<<<592, 256>>>(x, xh, MTOT * DIM / 4);

    // 2) Q/K/V projections — grid (8, 16) = 128 CTAs = one full wave
    dim3 gemm_grid(DIM / 128, MTOT / 256);
    gemm_f16_kernel<<<gemm_grid, 256, GEMM_SMEM>>>(xh, wqt, nullptr, qh,  nullptr, nullptr, 1);
    gemm_f16_kernel<<<gemm_grid, 256, GEMM_SMEM>>>(xh, wkt, nullptr, khi, klo,     nullptr, 2);
    gemm_f16_kernel<<<gemm_grid, 256, GEMM_SMEM>>>(xh, wvt, nullptr, vt,  nullptr, nullptr, 3);

    // 3) attention (fp16 output)
    dim3 attn_grid(SEQ / 64, NH, BATCH);     // (32, 16, 2)
    attn_tc_kernel<<<attn_grid, 128, ATTN_SMEM>>>(qh, khi, klo, vt, ah);

    // 4) output projection (+bias, fp32 out)
    gemm_f16_kernel<<<gemm_grid, 256, GEMM_SMEM>>>(ah, wot, out, nullptr, nullptr, bo, 0);
}

// round 15
// speedup vs baseline: 1.1544x; 1.1544x over previous
#include <cuda_runtime.h>
#include <cuda_fp16.h>
#include <math.h>
#include <stdint.h>

#define BATCH 2
#define SEQ   2048
#define DIM   1024
#define NH    16
#define HD    64
#define MTOT  (BATCH*SEQ)   // 4096

// ---------------------------------------------------------------------------
// Scratch (allocation-free rule: __device__ globals)
// ---------------------------------------------------------------------------
__device__ __half g_xh[MTOT*DIM];     // x as fp16
__device__ __half g_ah[MTOT*DIM];     // attention output, fp16
__device__ __half g_qh[MTOT*DIM];     // Q, prescaled, fp16
__device__ __half g_kh[MTOT*DIM];     // K fp16
__device__ __half g_vt[MTOT*DIM];     // V fp16, transposed: [b,h][d][s]
// Transposed weights as fp16: WT[n][k] = fp16(W[k][n])
__device__ __half g_wqt[DIM*DIM];
__device__ __half g_wkt[DIM*DIM];
__device__ __half g_wvt[DIM*DIM];
__device__ __half g_wot[DIM*DIM];

struct Ptr4 { const float* W[4]; __half* WT[4]; };

// ---------------------------------------------------------------------------
// Helpers
// ---------------------------------------------------------------------------
__device__ __forceinline__ uint32_t h2bits(__half2 h) {
    return *reinterpret_cast<uint32_t*>(&h);
}
__device__ __forceinline__ uint32_t smem_u32(const void* p) {
    uint32_t a;
    asm("{ .reg .u64 t; cvta.to.shared.u64 t, %1; cvt.u32.u64 %0, t; }"
        : "=r"(a) : "l"(p));
    return a;
}

#define MMA_F16(d, a, b0, b1) \
    asm volatile("mma.sync.aligned.m16n8k16.row.col.f32.f16.f16.f32 " \
        "{%0,%1,%2,%3}, {%4,%5,%6,%7}, {%8,%9}, {%0,%1,%2,%3};" \
        : "+f"((d)[0]), "+f"((d)[1]), "+f"((d)[2]), "+f"((d)[3]) \
        : "r"((a)[0]), "r"((a)[1]), "r"((a)[2]), "r"((a)[3]), \
          "r"(b0), "r"(b1))

#define CP_ASYNC16(dst_u32, src_ptr) \
    asm volatile("cp.async.cg.shared.global [%0], [%1], 16;" \
        :: "r"(dst_u32), "l"(src_ptr))
#define CP_COMMIT() asm volatile("cp.async.commit_group;" ::: "memory")
#define CP_WAIT0()  asm volatile("cp.async.wait_group 0;"  ::: "memory")
#define CP_WAIT1()  asm volatile("cp.async.wait_group 1;"  ::: "memory")

// ---------------------------------------------------------------------------
// x fp32 -> fp16 (one shot)
// ---------------------------------------------------------------------------
__global__ __launch_bounds__(256) void f32_to_f16_kernel(
    const float* __restrict__ src, __half* __restrict__ dst, int n4)
{
    int i = blockIdx.x * blockDim.x + threadIdx.x;
    int stride = gridDim.x * blockDim.x;
    for (; i < n4; i += stride) {
        float4 v = reinterpret_cast<const float4*>(src)[i];
        uint2 w;
        w.x = h2bits(__floats2half2_rn(v.x, v.y));
        w.y = h2bits(__floats2half2_rn(v.z, v.w));
        reinterpret_cast<uint2*>(dst)[i] = w;
    }
}

// ---------------------------------------------------------------------------
// Fused transpose + fp16-convert: all 4 weights in one launch (z selects)
// ---------------------------------------------------------------------------
__global__ __launch_bounds__(256) void transpose_f16_kernel(Ptr4 p)
{
    __shared__ float tile[32][33];
    const float* W  = p.W[blockIdx.z];
    __half*      WT = p.WT[blockIdx.z];
    const int k0 = blockIdx.y * 32;
    const int n0 = blockIdx.x * 32;
    const int tx = threadIdx.x;
    const int ty = threadIdx.y;
    #pragma unroll
    for (int i = ty; i < 32; i += 8)
        tile[i][tx] = W[(size_t)(k0 + i) * DIM + n0 + tx];
    __syncthreads();
    #pragma unroll
    for (int i = ty; i < 32; i += 8)
        WT[(size_t)(n0 + i) * DIM + k0 + tx] = __float2half_rn(tile[tx][i]);
}

// ---------------------------------------------------------------------------
// fp16 GEMM (R13 proven config): CTA 256x128, 8 warps (4M x 2N, 64x64),
// BK=32, cp.async 2-stage, scalar fragment loads. 128 CTAs = one wave.
// Epilogue modes: 0: Cf=v+bias | 1: Ch=fp16(v/8) | 2: Ch=fp16(v)
//                 3: Ch=fp16(v) transposed to [b,h][d][s]
// ---------------------------------------------------------------------------
#define GSTR    20
#define GSTAGE_A (256*GSTR)
#define GSTAGE_B (128*GSTR)
#define GBUF     (GSTAGE_A + GSTAGE_B)
#define GEMM_SMEM (2*GBUF*4)       // 61440 B

__global__ __launch_bounds__(256, 1) void gemm_f16_kernel(
    const __half* __restrict__ Ah, const __half* __restrict__ BT,
    float* __restrict__ Cf, __half* __restrict__ Ch,
    const float* __restrict__ bias, int mode)
{
    extern __shared__ uint32_t smw[];
    const int tid  = threadIdx.x;
    const int lane = tid & 31;
    const int wid  = tid >> 5;
    const int wm   = wid & 3;
    const int wn   = wid >> 2;
    const int gid  = lane >> 2;
    const int tig  = lane & 3;
    const int bx   = blockIdx.x;
    const int by   = blockIdx.y;

    const int lrow = tid >> 2;
    const int lseg = tid & 3;

    const __half* Ag = Ah + (size_t)(by * 256) * DIM;
    const __half* Bg = BT + (size_t)(bx * 128) * DIM;
    const uint32_t sbase = smem_u32(smw);

    auto prefetch = [&](int s) {
        const uint32_t base = sbase + (uint32_t)(s & 1) * (GBUF * 4);
        const int kof = s * 32 + lseg * 8;
        #pragma unroll
        for (int i = 0; i < 4; i++) {
            const int row = lrow + i * 64;
            CP_ASYNC16(base + (uint32_t)((row * GSTR + lseg * 4) * 4),
                       Ag + (size_t)row * DIM + kof);
        }
        #pragma unroll
        for (int i = 0; i < 2; i++) {
            const int row = lrow + i * 64;
            CP_ASYNC16(base + (uint32_t)((GSTAGE_A + row * GSTR + lseg * 4) * 4),
                       Bg + (size_t)row * DIM + kof);
        }
        CP_COMMIT();
    };

    float c[4][8][4];
    #pragma unroll
    for (int i = 0; i < 4; i++)
        #pragma unroll
        for (int j = 0; j < 8; j++)
            #pragma unroll
            for (int k = 0; k < 4; k++)
                c[i][j][k] = 0.0f;

    prefetch(0);
    prefetch(1);

    const int NS = DIM / 32;
    for (int s = 0; s < NS; s++) {
        if (s + 1 < NS) { CP_WAIT1(); } else { CP_WAIT0(); }
        __syncthreads();

        const uint32_t* Au = smw + (s & 1) * GBUF;
        const uint32_t* Bu = Au + GSTAGE_A;

        #pragma unroll
        for (int kt = 0; kt < 2; kt++) {
            uint32_t af[4][4], bf[8][2];
            const int ko = kt * 8 + tig;
            #pragma unroll
            for (int am = 0; am < 4; am++) {
                const uint32_t* p = Au + (wm * 64 + am * 16 + gid) * GSTR + ko;
                af[am][0] = p[0];
                af[am][1] = p[8 * GSTR];
                af[am][2] = p[4];
                af[am][3] = p[8 * GSTR + 4];
            }
            #pragma unroll
            for (int bn = 0; bn < 8; bn++) {
                const uint32_t* p = Bu + (wn * 64 + bn * 8 + gid) * GSTR + ko;
                bf[bn][0] = p[0];
                bf[bn][1] = p[4];
            }
            #pragma unroll
            for (int am = 0; am < 4; am++)
                #pragma unroll
                for (int bn = 0; bn < 8; bn++)
                    MMA_F16(c[am][bn], af[am], bf[bn][0], bf[bn][1]);
        }

        __syncthreads();
        if (s + 2 < NS) prefetch(s + 2);
    }

    const int rbase = by * 256 + wm * 64 + gid;
    const int cbase = bx * 128 + wn * 64 + tig * 2;
    #pragma unroll
    for (int am = 0; am < 4; am++) {
        #pragma unroll
        for (int bn = 0; bn < 8; bn++) {
            const int col = cbase + bn * 8;
            const int r0  = rbase + am * 16;
            const float v00 = c[am][bn][0], v01 = c[am][bn][1];
            const float v10 = c[am][bn][2], v11 = c[am][bn][3];
            if (mode == 0) {
                float b0 = bias[col], b1 = bias[col + 1];
                *reinterpret_cast<float2*>(Cf + (size_t)r0 * DIM + col) =
                    make_float2(v00 + b0, v01 + b1);
                *reinterpret_cast<float2*>(Cf + (size_t)(r0 + 8) * DIM + col) =
                    make_float2(v10 + b0, v11 + b1);
            } else if (mode == 1) {
                reinterpret_cast<uint32_t*>(Ch)[((size_t)r0 * DIM + col) >> 1] =
                    h2bits(__floats2half2_rn(v00 * 0.125f, v01 * 0.125f));
                reinterpret_cast<uint32_t*>(Ch)[((size_t)(r0 + 8) * DIM + col) >> 1] =
                    h2bits(__floats2half2_rn(v10 * 0.125f, v11 * 0.125f));
            } else if (mode == 2) {
                reinterpret_cast<uint32_t*>(Ch)[((size_t)r0 * DIM + col) >> 1] =
                    h2bits(__floats2half2_rn(v00, v01));
                reinterpret_cast<uint32_t*>(Ch)[((size_t)(r0 + 8) * DIM + col) >> 1] =
                    h2bits(__floats2half2_rn(v10, v11));
            } else {
                const size_t bb = (size_t)(r0 >> 11) * 2097152;
                const int s0 = r0 & 2047;
                Ch[bb + (size_t)col * 2048 + s0]           = __float2half_rn(v00);
                Ch[bb + (size_t)(col + 1) * 2048 + s0]     = __float2half_rn(v01);
                Ch[bb + (size_t)col * 2048 + s0 + 8]       = __float2half_rn(v10);
                Ch[bb + (size_t)(col + 1) * 2048 + s0 + 8] = __float2half_rn(v11);
            }
        }
    }
}

// ---------------------------------------------------------------------------
// Tensor-core flash attention v7 (causal): SINGLE-term fp16 QK + fp16 PV.
// (R11 empirically showed each dropped lo-term costs only ~1.9e-4 in quad.)
// Pure-copy tiles, 128 thr = 4 warps, 64 q rows, kv tiles of 64.
// Smem: PpW | Kh | Vp, each [64][36] words -> 27648 B.
// ---------------------------------------------------------------------------
#define ATTN_SMEM (3*64*36*4)    // 27648 B

__global__ __launch_bounds__(128, 4) void attn_tc_kernel(
    const __half* __restrict__ Qh, const __half* __restrict__ Kh,
    const __half* __restrict__ Vt, __half* __restrict__ Oout)
{
    extern __shared__ uint32_t smw[];
    uint32_t* PpW = smw;
    uint32_t* KhU = smw + 64 * 36;
    uint32_t* VpW = KhU + 64 * 36;

    const int b    = blockIdx.z;
    const int h    = blockIdx.y;
    const int q0   = (gridDim.x - 1 - blockIdx.x) * 64;
    const int tid  = threadIdx.x;
    const int wq   = tid >> 5;
    const int lane = tid & 31;
    const int gid  = lane >> 2;
    const int tig  = lane & 3;

    const __half* Qg  = Qh + ((size_t)b * SEQ + q0) * DIM + h * HD;
    const __half* Khg = Kh + (size_t)b * SEQ * DIM + h * HD;
    const __half* Vtg = Vt + (size_t)(b * NH + h) * (HD * SEQ);

    #pragma unroll
    for (int i = 0; i < 4; i++) {
        int idx = tid + i * 128;
        int r = idx >> 3, seg = idx & 7;
        *reinterpret_cast<uint4*>(PpW + r * 36 + seg * 4) =
            *reinterpret_cast<const uint4*>(Qg + (size_t)r * DIM + seg * 8);
    }
    __syncthreads();

    uint32_t qh[4][4];
    {
        const int rr = wq * 16 + gid;
        #pragma unroll
        for (int kt = 0; kt < 4; kt++) {
            qh[kt][0] = PpW[rr * 36 + kt * 8 + tig];
            qh[kt][1] = PpW[(rr + 8) * 36 + kt * 8 + tig];
            qh[kt][2] = PpW[rr * 36 + kt * 8 + 4 + tig];
            qh[kt][3] = PpW[(rr + 8) * 36 + kt * 8 + 4 + tig];
        }
    }

    float m0 = -1e30f, m1 = -1e30f, l0 = 0.0f, l1 = 0.0f;
    float o[8][4];
    #pragma unroll
    for (int nt = 0; nt < 8; nt++)
        #pragma unroll
        for (int e = 0; e < 4; e++) o[nt][e] = 0.0f;

    const int ntiles = (q0 >> 6) + 1;
    for (int t = 0; t < ntiles; t++) {
        const int kv0 = t * 64;
        __syncthreads();
        #pragma unroll
        for (int i = 0; i < 4; i++) {
            int idx = tid + i * 128;
            int r = idx >> 3, seg = idx & 7;
            *reinterpret_cast<uint4*>(KhU + r * 36 + seg * 4) =
                *reinterpret_cast<const uint4*>(Khg + (size_t)(kv0 + r) * DIM + seg * 8);
            *reinterpret_cast<uint4*>(VpW + r * 36 + seg * 4) =
                *reinterpret_cast<const uint4*>(Vtg + (size_t)r * SEQ + kv0 + seg * 8);
        }
        __syncthreads();

        float s[8][4];
        #pragma unroll
        for (int nt = 0; nt < 8; nt++)
            #pragma unroll
            for (int e = 0; e < 4; e++) s[nt][e] = 0.0f;

        #pragma unroll
        for (int kt = 0; kt < 4; kt++) {
            #pragma unroll
            for (int nt = 0; nt < 8; nt++) {
                const int boff = (nt * 8 + gid) * 36 + kt * 8 + tig;
                MMA_F16(s[nt], qh[kt], KhU[boff], KhU[boff + 4]);
            }
        }

        const int r0g = q0 + wq * 16 + gid;
        const int r1g = r0g + 8;
        if (kv0 == q0) {
            #pragma unroll
            for (int nt = 0; nt < 8; nt++) {
                const int c0 = kv0 + nt * 8 + 2 * tig;
                if (c0     > r0g) s[nt][0] = -1e30f;
                if (c0 + 1 > r0g) s[nt][1] = -1e30f;
                if (c0     > r1g) s[nt][2] = -1e30f;
                if (c0 + 1 > r1g) s[nt][3] = -1e30f;
            }
        }

        float mx0 = -1e30f, mx1 = -1e30f;
        #pragma unroll
        for (int nt = 0; nt < 8; nt++) {
            mx0 = fmaxf(mx0, fmaxf(s[nt][0], s[nt][1]));
            mx1 = fmaxf(mx1, fmaxf(s[nt][2], s[nt][3]));
        }
        mx0 = fmaxf(mx0, __shfl_xor_sync(0xffffffffu, mx0, 1));
        mx0 = fmaxf(mx0, __shfl_xor_sync(0xffffffffu, mx0, 2));
        mx1 = fmaxf(mx1, __shfl_xor_sync(0xffffffffu, mx1, 1));
        mx1 = fmaxf(mx1, __shfl_xor_sync(0xffffffffu, mx1, 2));

        const float nm0 = fmaxf(m0, mx0);
        const float nm1 = fmaxf(m1, mx1);
        const float sc0 = __expf(m0 - nm0);
        const float sc1 = __expf(m1 - nm1);
        m0 = nm0; m1 = nm1;
        l0 *= sc0; l1 *= sc1;

        float sum0 = 0.0f, sum1 = 0.0f;
        const int prow = wq * 16 + gid;
        #pragma unroll
        for (int nt = 0; nt < 8; nt++) {
            float p00 = __expf(s[nt][0] - m0);
            float p01 = __expf(s[nt][1] - m0);
            float p10 = __expf(s[nt][2] - m1);
            float p11 = __expf(s[nt][3] - m1);
            sum0 += p00 + p01;
            sum1 += p10 + p11;
            PpW[prow * 36 + nt * 4 + tig]       = h2bits(__floats2half2_rn(p00, p01));
            PpW[(prow + 8) * 36 + nt * 4 + tig] = h2bits(__floats2half2_rn(p10, p11));
            o[nt][0] *= sc0; o[nt][1] *= sc0;
            o[nt][2] *= sc1; o[nt][3] *= sc1;
        }
        sum0 += __shfl_xor_sync(0xffffffffu, sum0, 1);
        sum0 += __shfl_xor_sync(0xffffffffu, sum0, 2);
        sum1 += __shfl_xor_sync(0xffffffffu, sum1, 1);
        sum1 += __shfl_xor_sync(0xffffffffu, sum1, 2);
        l0 += sum0; l1 += sum1;

        __syncwarp();

        #pragma unroll
        for (int kt = 0; kt < 4; kt++) {
            uint32_t a[4];
            a[0] = PpW[prow * 36 + kt * 8 + tig];
            a[1] = PpW[(prow + 8) * 36 + kt * 8 + tig];
            a[2] = PpW[prow * 36 + kt * 8 + 4 + tig];
            a[3] = PpW[(prow + 8) * 36 + kt * 8 + 4 + tig];
            #pragma unroll
            for (int nt = 0; nt < 8; nt++) {
                const int voff = (nt * 8 + gid) * 36 + kt * 8 + tig;
                MMA_F16(o[nt], a, VpW[voff], VpW[voff + 4]);
            }
        }
        __syncwarp();
    }

    const float inv0 = 1.0f / l0;
    const float inv1 = 1.0f / l1;
    const int r0g = q0 + wq * 16 + gid;
    uint32_t* OgW = reinterpret_cast<uint32_t*>(
        Oout + (size_t)b * SEQ * DIM + h * HD);
    #pragma unroll
    for (int nt = 0; nt < 8; nt++) {
        const int col = nt * 8 + 2 * tig;
        OgW[((size_t)r0g * DIM + col) >> 1] =
            h2bits(__floats2half2_rn(o[nt][0] * inv0, o[nt][1] * inv0));
        OgW[((size_t)(r0g + 8) * DIM + col) >> 1] =
            h2bits(__floats2half2_rn(o[nt][2] * inv1, o[nt][3] * inv1));
    }
}

// ---------------------------------------------------------------------------
// Launch
// ---------------------------------------------------------------------------
extern "C" void kernel_launch(void* const* d_in, const int* in_sizes, int n_in,
                              void* d_out, int out_size)
{
    const float* x  = (const float*)d_in[0];
    const float* Wq = (const float*)d_in[1];
    const float* Wk = (const float*)d_in[2];
    const float* Wv = (const float*)d_in[3];
    const float* Wo = (const float*)d_in[4];
    const float* bo = (const float*)d_in[5];
    float* out = (float*)d_out;

    __half *xh, *ah, *qh, *kh, *vt, *wqt, *wkt, *wvt, *wot;
    cudaGetSymbolAddress((void**)&xh,  g_xh);
    cudaGetSymbolAddress((void**)&ah,  g_ah);
    cudaGetSymbolAddress((void**)&qh,  g_qh);
    cudaGetSymbolAddress((void**)&kh,  g_kh);
    cudaGetSymbolAddress((void**)&vt,  g_vt);
    cudaGetSymbolAddress((void**)&wqt, g_wqt);
    cudaGetSymbolAddress((void**)&wkt, g_wkt);
    cudaGetSymbolAddress((void**)&wvt, g_wvt);
    cudaGetSymbolAddress((void**)&wot, g_wot);

    cudaFuncSetAttribute(gemm_f16_kernel,
                         cudaFuncAttributeMaxDynamicSharedMemorySize, GEMM_SMEM);
    cudaFuncSetAttribute(attn_tc_kernel,
                         cudaFuncAttributeMaxDynamicSharedMemorySize, ATTN_SMEM);

    // 1) weight transposes (fused) + x -> fp16
    Ptr4 tp;
    tp.W[0] = Wq;   tp.W[1] = Wk;   tp.W[2] = Wv;   tp.W[3] = Wo;
    tp.WT[0] = wqt; tp.WT[1] = wkt; tp.WT[2] = wvt; tp.WT[3] = wot;
    dim3 wt_grid(DIM / 32, DIM / 32, 4);
    dim3 wt_block(32, 8);
    transpose_f16_kernel<<<wt_grid, wt_block>>>(tp);
    f32_to_f16_kernel<<<592, 256>>>(x, xh, MTOT * DIM / 4);

    // 2) Q/K/V projections — 128 CTAs = one full wave each
    dim3 gemm_grid(DIM / 128, MTOT / 256);
    gemm_f16_kernel<<<gemm_grid, 256, GEMM_SMEM>>>(xh, wqt, nullptr, qh, nullptr, 1);
    gemm_f16_kernel<<<gemm_grid, 256, GEMM_SMEM>>>(xh, wkt, nullptr, kh, nullptr, 2);
    gemm_f16_kernel<<<gemm_grid, 256, GEMM_SMEM>>>(xh, wvt, nullptr, vt, nullptr, 3);

    // 3) attention (1-term fp16 QK, fp16 PV, fp16 output)
    dim3 attn_grid(SEQ / 64, NH, BATCH);     // (32, 16, 2)
    attn_tc_kernel<<<attn_grid, 128, ATTN_SMEM>>>(qh, kh, vt, ah);

    // 4) output projection (+bias, fp32 out)
    gemm_f16_kernel<<<gemm_grid, 256, GEMM_SMEM>>>(ah, wot, out, nullptr, bo, 0);
}

// round 16
// speedup vs baseline: 1.1585x; 1.0035x over previous
#include <cuda_runtime.h>
#include <cuda_fp16.h>
#include <math.h>
#include <stdint.h>

#define BATCH 2
#define SEQ   2048
#define DIM   1024
#define NH    16
#define HD    64
#define MTOT  (BATCH*SEQ)   // 4096

// ---------------------------------------------------------------------------
// Scratch (allocation-free rule: __device__ globals)
// ---------------------------------------------------------------------------
__device__ __half g_xh[MTOT*DIM];     // x as fp16
__device__ __half g_ah[MTOT*DIM];     // attention output, fp16
__device__ __half g_qh[MTOT*DIM];     // Q, prescaled, fp16
__device__ __half g_kh[MTOT*DIM];     // K fp16
__device__ __half g_vt[MTOT*DIM];     // V fp16, transposed: [b,h][d][s]
// Transposed weights as fp16: WT[n][k] = fp16(W[k][n])
__device__ __half g_wqt[DIM*DIM];
__device__ __half g_wkt[DIM*DIM];
__device__ __half g_wvt[DIM*DIM];
__device__ __half g_wot[DIM*DIM];

struct Ptr4 { const float* W[4]; __half* WT[4]; };

// ---------------------------------------------------------------------------
// Helpers
// ---------------------------------------------------------------------------
__device__ __forceinline__ uint32_t h2bits(__half2 h) {
    return *reinterpret_cast<uint32_t*>(&h);
}
__device__ __forceinline__ uint32_t smem_u32(const void* p) {
    uint32_t a;
    asm("{ .reg .u64 t; cvta.to.shared.u64 t, %1; cvt.u32.u64 %0, t; }"
        : "=r"(a) : "l"(p));
    return a;
}

#define MMA_F16(d, a, b0, b1) \
    asm volatile("mma.sync.aligned.m16n8k16.row.col.f32.f16.f16.f32 " \
        "{%0,%1,%2,%3}, {%4,%5,%6,%7}, {%8,%9}, {%0,%1,%2,%3};" \
        : "+f"((d)[0]), "+f"((d)[1]), "+f"((d)[2]), "+f"((d)[3]) \
        : "r"((a)[0]), "r"((a)[1]), "r"((a)[2]), "r"((a)[3]), \
          "r"(b0), "r"(b1))

#define CP_ASYNC16(dst_u32, src_ptr) \
    asm volatile("cp.async.cg.shared.global [%0], [%1], 16;" \
        :: "r"(dst_u32), "l"(src_ptr))
#define CP_COMMIT() asm volatile("cp.async.commit_group;" ::: "memory")
#define CP_WAIT0()  asm volatile("cp.async.wait_group 0;"  ::: "memory")
#define CP_WAIT1()  asm volatile("cp.async.wait_group 1;"  ::: "memory")

// ---------------------------------------------------------------------------
// Fused prep: z=0..3 weight transpose+fp16; z=4 x -> fp16
// ---------------------------------------------------------------------------
__global__ __launch_bounds__(256) void prep_kernel(
    Ptr4 p, const float* __restrict__ x, __half* __restrict__ xh)
{
    if (blockIdx.z < 4) {
        __shared__ float tile[32][33];
        const float* W  = p.W[blockIdx.z];
        __half*      WT = p.WT[blockIdx.z];
        const int k0 = blockIdx.y * 32;
        const int n0 = blockIdx.x * 32;
        const int tx = threadIdx.x & 31;
        const int ty = threadIdx.x >> 5;
        #pragma unroll
        for (int i = ty; i < 32; i += 8)
            tile[i][tx] = W[(size_t)(k0 + i) * DIM + n0 + tx];
        __syncthreads();
        #pragma unroll
        for (int i = ty; i < 32; i += 8)
            WT[(size_t)(n0 + i) * DIM + k0 + tx] = __float2half_rn(tile[tx][i]);
    } else {
        // 1024 blocks cover 4M floats: 4096 per block, 16 per thread
        const size_t base = ((size_t)(blockIdx.x + 32 * blockIdx.y)) * 4096
                          + threadIdx.x * 4;
        #pragma unroll
        for (int i = 0; i < 4; i++) {
            float4 v = *reinterpret_cast<const float4*>(x + base + i * 1024);
            uint2 w;
            w.x = h2bits(__floats2half2_rn(v.x, v.y));
            w.y = h2bits(__floats2half2_rn(v.z, v.w));
            *reinterpret_cast<uint2*>(xh + base + i * 1024) = w;
        }
    }
}

// ---------------------------------------------------------------------------
// fp16 GEMM v5: CTA 256x128, 8 warps (4M x 2N, 64x64), BK=32, cp.async
// 3-STAGE pipeline — ONE barrier per stage, prefetch issued before compute.
// Grid = (DIM/128, MTOT/256) = 128 CTAs = one wave.
// Epilogue modes: 0: Cf=v+bias | 1: Ch=fp16(v/8) | 2: Ch=fp16(v)
//                 3: Ch=fp16(v) transposed to [b,h][d][s]
// ---------------------------------------------------------------------------
#define GSTR    20
#define GSTAGE_A (256*GSTR)
#define GSTAGE_B (128*GSTR)
#define GBUF     (GSTAGE_A + GSTAGE_B)
#define GEMM_SMEM (3*GBUF*4)       // 92160 B

__global__ __launch_bounds__(256, 1) void gemm_f16_kernel(
    const __half* __restrict__ Ah, const __half* __restrict__ BT,
    float* __restrict__ Cf, __half* __restrict__ Ch,
    const float* __restrict__ bias, int mode)
{
    extern __shared__ uint32_t smw[];
    const int tid  = threadIdx.x;
    const int lane = tid & 31;
    const int wid  = tid >> 5;
    const int wm   = wid & 3;
    const int wn   = wid >> 2;
    const int gid  = lane >> 2;
    const int tig  = lane & 3;
    const int bx   = blockIdx.x;
    const int by   = blockIdx.y;

    const int lrow = tid >> 2;
    const int lseg = tid & 3;

    const __half* Ag = Ah + (size_t)(by * 256) * DIM;
    const __half* Bg = BT + (size_t)(bx * 128) * DIM;
    const uint32_t sbase = smem_u32(smw);

    auto prefetch = [&](int s) {
        const uint32_t base = sbase + (uint32_t)(s % 3) * (GBUF * 4);
        const int kof = s * 32 + lseg * 8;
        #pragma unroll
        for (int i = 0; i < 4; i++) {
            const int row = lrow + i * 64;
            CP_ASYNC16(base + (uint32_t)((row * GSTR + lseg * 4) * 4),
                       Ag + (size_t)row * DIM + kof);
        }
        #pragma unroll
        for (int i = 0; i < 2; i++) {
            const int row = lrow + i * 64;
            CP_ASYNC16(base + (uint32_t)((GSTAGE_A + row * GSTR + lseg * 4) * 4),
                       Bg + (size_t)row * DIM + kof);
        }
        CP_COMMIT();
    };

    float c[4][8][4];
    #pragma unroll
    for (int i = 0; i < 4; i++)
        #pragma unroll
        for (int j = 0; j < 8; j++)
            #pragma unroll
            for (int k = 0; k < 4; k++)
                c[i][j][k] = 0.0f;

    prefetch(0);
    prefetch(1);

    const int NS = DIM / 32;
    for (int s = 0; s < NS; s++) {
        if (s + 1 < NS) { CP_WAIT1(); } else { CP_WAIT0(); }
        __syncthreads();
        // Safe: buffer (s+2)%3 == (s-1)%3 was fully consumed before the
        // barrier above (compute of stage s-1 precedes it in program order).
        if (s + 2 < NS) prefetch(s + 2);

        const uint32_t* Au = smw + (s % 3) * GBUF;
        const uint32_t* Bu = Au + GSTAGE_A;

        #pragma unroll
        for (int kt = 0; kt < 2; kt++) {
            uint32_t af[4][4], bf[8][2];
            const int ko = kt * 8 + tig;
            #pragma unroll
            for (int am = 0; am < 4; am++) {
                const uint32_t* p = Au + (wm * 64 + am * 16 + gid) * GSTR + ko;
                af[am][0] = p[0];
                af[am][1] = p[8 * GSTR];
                af[am][2] = p[4];
                af[am][3] = p[8 * GSTR + 4];
            }
            #pragma unroll
            for (int bn = 0; bn < 8; bn++) {
                const uint32_t* p = Bu + (wn * 64 + bn * 8 + gid) * GSTR + ko;
                bf[bn][0] = p[0];
                bf[bn][1] = p[4];
            }
            #pragma unroll
            for (int am = 0; am < 4; am++)
                #pragma unroll
                for (int bn = 0; bn < 8; bn++)
                    MMA_F16(c[am][bn], af[am], bf[bn][0], bf[bn][1]);
        }
    }

    const int rbase = by * 256 + wm * 64 + gid;
    const int cbase = bx * 128 + wn * 64 + tig * 2;
    #pragma unroll
    for (int am = 0; am < 4; am++) {
        #pragma unroll
        for (int bn = 0; bn < 8; bn++) {
            const int col = cbase + bn * 8;
            const int r0  = rbase + am * 16;
            const float v00 = c[am][bn][0], v01 = c[am][bn][1];
            const float v10 = c[am][bn][2], v11 = c[am][bn][3];
            if (mode == 0) {
                float b0 = bias[col], b1 = bias[col + 1];
                *reinterpret_cast<float2*>(Cf + (size_t)r0 * DIM + col) =
                    make_float2(v00 + b0, v01 + b1);
                *reinterpret_cast<float2*>(Cf + (size_t)(r0 + 8) * DIM + col) =
                    make_float2(v10 + b0, v11 + b1);
            } else if (mode == 1) {
                reinterpret_cast<uint32_t*>(Ch)[((size_t)r0 * DIM + col) >> 1] =
                    h2bits(__floats2half2_rn(v00 * 0.125f, v01 * 0.125f));
                reinterpret_cast<uint32_t*>(Ch)[((size_t)(r0 + 8) * DIM + col) >> 1] =
                    h2bits(__floats2half2_rn(v10 * 0.125f, v11 * 0.125f));
            } else if (mode == 2) {
                reinterpret_cast<uint32_t*>(Ch)[((size_t)r0 * DIM + col) >> 1] =
                    h2bits(__floats2half2_rn(v00, v01));
                reinterpret_cast<uint32_t*>(Ch)[((size_t)(r0 + 8) * DIM + col) >> 1] =
                    h2bits(__floats2half2_rn(v10, v11));
            } else {
                const size_t bb = (size_t)(r0 >> 11) * 2097152;
                const int s0 = r0 & 2047;
                Ch[bb + (size_t)col * 2048 + s0]           = __float2half_rn(v00);
                Ch[bb + (size_t)(col + 1) * 2048 + s0]     = __float2half_rn(v01);
                Ch[bb + (size_t)col * 2048 + s0 + 8]       = __float2half_rn(v10);
                Ch[bb + (size_t)(col + 1) * 2048 + s0 + 8] = __float2half_rn(v11);
            }
        }
    }
}

// ---------------------------------------------------------------------------
// Tensor-core flash attention (R15 proven): 1-term fp16 QK + fp16 PV.
// Pure-copy tiles, 128 thr = 4 warps, 64 q rows, kv tiles of 64.
// ---------------------------------------------------------------------------
#define ATTN_SMEM (3*64*36*4)    // 27648 B

__global__ __launch_bounds__(128, 4) void attn_tc_kernel(
    const __half* __restrict__ Qh, const __half* __restrict__ Kh,
    const __half* __restrict__ Vt, __half* __restrict__ Oout)
{
    extern __shared__ uint32_t smw[];
    uint32_t* PpW = smw;
    uint32_t* KhU = smw + 64 * 36;
    uint32_t* VpW = KhU + 64 * 36;

    const int b    = blockIdx.z;
    const int h    = blockIdx.y;
    const int q0   = (gridDim.x - 1 - blockIdx.x) * 64;
    const int tid  = threadIdx.x;
    const int wq   = tid >> 5;
    const int lane = tid & 31;
    const int gid  = lane >> 2;
    const int tig  = lane & 3;

    const __half* Qg  = Qh + ((size_t)b * SEQ + q0) * DIM + h * HD;
    const __half* Khg = Kh + (size_t)b * SEQ * DIM + h * HD;
    const __half* Vtg = Vt + (size_t)(b * NH + h) * (HD * SEQ);

    #pragma unroll
    for (int i = 0; i < 4; i++) {
        int idx = tid + i * 128;
        int r = idx >> 3, seg = idx & 7;
        *reinterpret_cast<uint4*>(PpW + r * 36 + seg * 4) =
            *reinterpret_cast<const uint4*>(Qg + (size_t)r * DIM + seg * 8);
    }
    __syncthreads();

    uint32_t qh[4][4];
    {
        const int rr = wq * 16 + gid;
        #pragma unroll
        for (int kt = 0; kt < 4; kt++) {
            qh[kt][0] = PpW[rr * 36 + kt * 8 + tig];
            qh[kt][1] = PpW[(rr + 8) * 36 + kt * 8 + tig];
            qh[kt][2] = PpW[rr * 36 + kt * 8 + 4 + tig];
            qh[kt][3] = PpW[(rr + 8) * 36 + kt * 8 + 4 + tig];
        }
    }

    float m0 = -1e30f, m1 = -1e30f, l0 = 0.0f, l1 = 0.0f;
    float o[8][4];
    #pragma unroll
    for (int nt = 0; nt < 8; nt++)
        #pragma unroll
        for (int e = 0; e < 4; e++) o[nt][e] = 0.0f;

    const int ntiles = (q0 >> 6) + 1;
    for (int t = 0; t < ntiles; t++) {
        const int kv0 = t * 64;
        __syncthreads();
        #pragma unroll
        for (int i = 0; i < 4; i++) {
            int idx = tid + i * 128;
            int r = idx >> 3, seg = idx & 7;
            *reinterpret_cast<uint4*>(KhU + r * 36 + seg * 4) =
                *reinterpret_cast<const uint4*>(Khg + (size_t)(kv0 + r) * DIM + seg * 8);
            *reinterpret_cast<uint4*>(VpW + r * 36 + seg * 4) =
                *reinterpret_cast<const uint4*>(Vtg + (size_t)r * SEQ + kv0 + seg * 8);
        }
        __syncthreads();

        float s[8][4];
        #pragma unroll
        for (int nt = 0; nt < 8; nt++)
            #pragma unroll
            for (int e = 0; e < 4; e++) s[nt][e] = 0.0f;

        #pragma unroll
        for (int kt = 0; kt < 4; kt++) {
            #pragma unroll
            for (int nt = 0; nt < 8; nt++) {
                const int boff = (nt * 8 + gid) * 36 + kt * 8 + tig;
                MMA_F16(s[nt], qh[kt], KhU[boff], KhU[boff + 4]);
            }
        }

        const int r0g = q0 + wq * 16 + gid;
        const int r1g = r0g + 8;
        if (kv0 == q0) {
            #pragma unroll
            for (int nt = 0; nt < 8; nt++) {
                const int c0 = kv0 + nt * 8 + 2 * tig;
                if (c0     > r0g) s[nt][0] = -1e30f;
                if (c0 + 1 > r0g) s[nt][1] = -1e30f;
                if (c0     > r1g) s[nt][2] = -1e30f;
                if (c0 + 1 > r1g) s[nt][3] = -1e30f;
            }
        }

        float mx0 = -1e30f, mx1 = -1e30f;
        #pragma unroll
        for (int nt = 0; nt < 8; nt++) {
            mx0 = fmaxf(mx0, fmaxf(s[nt][0], s[nt][1]));
            mx1 = fmaxf(mx1, fmaxf(s[nt][2], s[nt][3]));
        }
        mx0 = fmaxf(mx0, __shfl_xor_sync(0xffffffffu, mx0, 1));
        mx0 = fmaxf(mx0, __shfl_xor_sync(0xffffffffu, mx0, 2));
        mx1 = fmaxf(mx1, __shfl_xor_sync(0xffffffffu, mx1, 1));
        mx1 = fmaxf(mx1, __shfl_xor_sync(0xffffffffu, mx1, 2));

        const float nm0 = fmaxf(m0, mx0);
        const float nm1 = fmaxf(m1, mx1);
        const float sc0 = __expf(m0 - nm0);
        const float sc1 = __expf(m1 - nm1);
        m0 = nm0; m1 = nm1;
        l0 *= sc0; l1 *= sc1;

        float sum0 = 0.0f, sum1 = 0.0f;
        const int prow = wq * 16 + gid;
        #pragma unroll
        for (int nt = 0; nt < 8; nt++) {
            float p00 = __expf(s[nt][0] - m0);
            float p01 = __expf(s[nt][1] - m0);
            float p10 = __expf(s[nt][2] - m1);
            float p11 = __expf(s[nt][3] - m1);
            sum0 += p00 + p01;
            sum1 += p10 + p11;
            PpW[prow * 36 + nt * 4 + tig]       = h2bits(__floats2half2_rn(p00, p01));
            PpW[(prow + 8) * 36 + nt * 4 + tig] = h2bits(__floats2half2_rn(p10, p11));
            o[nt][0] *= sc0; o[nt][1] *= sc0;
            o[nt][2] *= sc1; o[nt][3] *= sc1;
        }
        sum0 += __shfl_xor_sync(0xffffffffu, sum0, 1);
        sum0 += __shfl_xor_sync(0xffffffffu, sum0, 2);
        sum1 += __shfl_xor_sync(0xffffffffu, sum1, 1);
        sum1 += __shfl_xor_sync(0xffffffffu, sum1, 2);
        l0 += sum0; l1 += sum1;

        __syncwarp();

        #pragma unroll
        for (int kt = 0; kt < 4; kt++) {
            uint32_t a[4];
            a[0] = PpW[prow * 36 + kt * 8 + tig];
            a[1] = PpW[(prow + 8) * 36 + kt * 8 + tig];
            a[2] = PpW[prow * 36 + kt * 8 + 4 + tig];
            a[3] = PpW[(prow + 8) * 36 + kt * 8 + 4 + tig];
            #pragma unroll
            for (int nt = 0; nt < 8; nt++) {
                const int voff = (nt * 8 + gid) * 36 + kt * 8 + tig;
                MMA_F16(o[nt], a, VpW[voff], VpW[voff + 4]);
            }
        }
        __syncwarp();
    }

    const float inv0 = 1.0f / l0;
    const float inv1 = 1.0f / l1;
    const int r0g = q0 + wq * 16 + gid;
    uint32_t* OgW = reinterpret_cast<uint32_t*>(
        Oout + (size_t)b * SEQ * DIM + h * HD);
    #pragma unroll
    for (int nt = 0; nt < 8; nt++) {
        const int col = nt * 8 + 2 * tig;
        OgW[((size_t)r0g * DIM + col) >> 1] =
            h2bits(__floats2half2_rn(o[nt][0] * inv0, o[nt][1] * inv0));
        OgW[((size_t)(r0g + 8) * DIM + col) >> 1] =
            h2bits(__floats2half2_rn(o[nt][2] * inv1, o[nt][3] * inv1));
    }
}

// ---------------------------------------------------------------------------
// Launch
// ---------------------------------------------------------------------------
extern "C" void kernel_launch(void* const* d_in, const int* in_sizes, int n_in,
                              void* d_out, int out_size)
{
    const float* x  = (const float*)d_in[0];
    const float* Wq = (const float*)d_in[1];
    const float* Wk = (const float*)d_in[2];
    const float* Wv = (const float*)d_in[3];
    const float* Wo = (const float*)d_in[4];
    const float* bo = (const float*)d_in[5];
    float* out = (float*)d_out;

    __half *xh, *ah, *qh, *kh, *vt, *wqt, *wkt, *wvt, *wot;
    cudaGetSymbolAddress((void**)&xh,  g_xh);
    cudaGetSymbolAddress((void**)&ah,  g_ah);
    cudaGetSymbolAddress((void**)&qh,  g_qh);
    cudaGetSymbolAddress((void**)&kh,  g_kh);
    cudaGetSymbolAddress((void**)&vt,  g_vt);
    cudaGetSymbolAddress((void**)&wqt, g_wqt);
    cudaGetSymbolAddress((void**)&wkt, g_wkt);
    cudaGetSymbolAddress((void**)&wvt, g_wvt);
    cudaGetSymbolAddress((void**)&wot, g_wot);

    cudaFuncSetAttribute(gemm_f16_kernel,
                         cudaFuncAttributeMaxDynamicSharedMemorySize, GEMM_SMEM);
    cudaFuncSetAttribute(attn_tc_kernel,
                         cudaFuncAttributeMaxDynamicSharedMemorySize, ATTN_SMEM);

    // 1) fused prep: 4 weight transposes + x -> fp16, one launch
    Ptr4 tp;
    tp.W[0] = Wq;   tp.W[1] = Wk;   tp.W[2] = Wv;   tp.W[3] = Wo;
    tp.WT[0] = wqt; tp.WT[1] = wkt; tp.WT[2] = wvt; tp.WT[3] = wot;
    dim3 prep_grid(DIM / 32, DIM / 32, 5);
    prep_kernel<<<prep_grid, 256>>>(tp, x, xh);

    // 2) Q/K/V projections — 128 CTAs = one full wave each
    dim3 gemm_grid(DIM / 128, MTOT / 256);
    gemm_f16_kernel<<<gemm_grid, 256, GEMM_SMEM>>>(xh, wqt, nullptr, qh, nullptr, 1);
    gemm_f16_kernel<<<gemm_grid, 256, GEMM_SMEM>>>(xh, wkt, nullptr, kh, nullptr, 2);
    gemm_f16_kernel<<<gemm_grid, 256, GEMM_SMEM>>>(xh, wvt, nullptr, vt, nullptr, 3);

    // 3) attention (1-term fp16 QK, fp16 PV, fp16 output)
    dim3 attn_grid(SEQ / 64, NH, BATCH);     // (32, 16, 2)
    attn_tc_kernel<<<attn_grid, 128, ATTN_SMEM>>>(qh, kh, vt, ah);

    // 4) output projection (+bias, fp32 out)
    gemm_f16_kernel<<<gemm_grid, 256, GEMM_SMEM>>>(ah, wot, out, nullptr, bo, 0);
}

// round 17
// speedup vs baseline: 1.2630x; 1.0902x over previous
#include <cuda_runtime.h>
#include <cuda_fp16.h>
#include <math.h>
#include <stdint.h>

#define BATCH 2
#define SEQ   2048
#define DIM   1024
#define NH    16
#define HD    64
#define MTOT  (BATCH*SEQ)   // 4096

// ---------------------------------------------------------------------------
// Scratch (allocation-free rule: __device__ globals)
// ---------------------------------------------------------------------------
__device__ __half g_xh[MTOT*DIM];     // x as fp16
__device__ __half g_ah[MTOT*DIM];     // attention output, fp16
__device__ __half g_qh[MTOT*DIM];     // Q, prescaled, fp16
__device__ __half g_kh[MTOT*DIM];     // K fp16
__device__ __half g_vt[MTOT*DIM];     // V fp16, transposed: [b,h][d][s]
// Transposed weights as fp16: WT[n][k] = fp16(W[k][n])
__device__ __half g_wqt[DIM*DIM];
__device__ __half g_wkt[DIM*DIM];
__device__ __half g_wvt[DIM*DIM];
__device__ __half g_wot[DIM*DIM];

struct Ptr4 { const float* W[4]; __half* WT[4]; };

// ---------------------------------------------------------------------------
// Helpers
// ---------------------------------------------------------------------------
__device__ __forceinline__ uint32_t h2bits(__half2 h) {
    return *reinterpret_cast<uint32_t*>(&h);
}
__device__ __forceinline__ uint32_t smem_u32(const void* p) {
    uint32_t a;
    asm("{ .reg .u64 t; cvta.to.shared.u64 t, %1; cvt.u32.u64 %0, t; }"
        : "=r"(a) : "l"(p));
    return a;
}

#define MMA_F16(d, a, b0, b1) \
    asm volatile("mma.sync.aligned.m16n8k16.row.col.f32.f16.f16.f32 " \
        "{%0,%1,%2,%3}, {%4,%5,%6,%7}, {%8,%9}, {%0,%1,%2,%3};" \
        : "+f"((d)[0]), "+f"((d)[1]), "+f"((d)[2]), "+f"((d)[3]) \
        : "r"((a)[0]), "r"((a)[1]), "r"((a)[2]), "r"((a)[3]), \
          "r"(b0), "r"(b1))

#define CP_ASYNC16(dst_u32, src_ptr) \
    asm volatile("cp.async.cg.shared.global [%0], [%1], 16;" \
        :: "r"(dst_u32), "l"(src_ptr))
#define CP_COMMIT() asm volatile("cp.async.commit_group;" ::: "memory")
#define CP_WAIT0()  asm volatile("cp.async.wait_group 0;"  ::: "memory")
#define CP_WAIT1()  asm volatile("cp.async.wait_group 1;"  ::: "memory")

// ---------------------------------------------------------------------------
// Fused prep: z=0..3 weight transpose+fp16; z=4 x -> fp16  (R16 proven)
// ---------------------------------------------------------------------------
__global__ __launch_bounds__(256) void prep_kernel(
    Ptr4 p, const float* __restrict__ x, __half* __restrict__ xh)
{
    if (blockIdx.z < 4) {
        __shared__ float tile[32][33];
        const float* W  = p.W[blockIdx.z];
        __half*      WT = p.WT[blockIdx.z];
        const int k0 = blockIdx.y * 32;
        const int n0 = blockIdx.x * 32;
        const int tx = threadIdx.x & 31;
        const int ty = threadIdx.x >> 5;
        #pragma unroll
        for (int i = ty; i < 32; i += 8)
            tile[i][tx] = W[(size_t)(k0 + i) * DIM + n0 + tx];
        __syncthreads();
        #pragma unroll
        for (int i = ty; i < 32; i += 8)
            WT[(size_t)(n0 + i) * DIM + k0 + tx] = __float2half_rn(tile[tx][i]);
    } else {
        const size_t base = ((size_t)(blockIdx.x + 32 * blockIdx.y)) * 4096
                          + threadIdx.x * 4;
        #pragma unroll
        for (int i = 0; i < 4; i++) {
            float4 v = *reinterpret_cast<const float4*>(x + base + i * 1024);
            uint2 w;
            w.x = h2bits(__floats2half2_rn(v.x, v.y));
            w.y = h2bits(__floats2half2_rn(v.z, v.w));
            *reinterpret_cast<uint2*>(xh + base + i * 1024) = w;
        }
    }
}

// ---------------------------------------------------------------------------
// fp16 GEMM v6: CTA 256x128, 8 warps (4M x 2N, 64x64), BK=64 (16 stages),
// cp.async 3-stage ring, one barrier per stage.
// Smem rows: 64 halves + 8 pad = 36 words (conflict-free fragment banks,
// layout proven in R9). 3 x 54 KB = 161.9 KB smem, 1 CTA/SM.
// Grid = (DIM/128, MTOT/256) = 128 CTAs = one wave.
// Epilogue modes: 0: Cf=v+bias | 1: Ch=fp16(v/8) | 2: Ch=fp16(v)
//                 3: Ch=fp16(v) transposed to [b,h][d][s]
// ---------------------------------------------------------------------------
#define GSTR     36
#define GSTAGE_A (256*GSTR)
#define GSTAGE_B (128*GSTR)
#define GBUF     (GSTAGE_A + GSTAGE_B)
#define GEMM_SMEM (3*GBUF*4)       // 165888 B

__global__ __launch_bounds__(256, 1) void gemm_f16_kernel(
    const __half* __restrict__ Ah, const __half* __restrict__ BT,
    float* __restrict__ Cf, __half* __restrict__ Ch,
    const float* __restrict__ bias, int mode)
{
    extern __shared__ uint32_t smw[];
    const int tid  = threadIdx.x;
    const int lane = tid & 31;
    const int wid  = tid >> 5;
    const int wm   = wid & 3;
    const int wn   = wid >> 2;
    const int gid  = lane >> 2;
    const int tig  = lane & 3;
    const int bx   = blockIdx.x;
    const int by   = blockIdx.y;

    const int lrow = tid >> 3;        // 0..31 (base row; +32 per i)
    const int lseg = tid & 7;         // 16B segment (8 halves) within 64-half row

    const __half* Ag = Ah + (size_t)(by * 256) * DIM;
    const __half* Bg = BT + (size_t)(bx * 128) * DIM;
    const uint32_t sbase = smem_u32(smw);

    auto prefetch = [&](int s) {
        const uint32_t base = sbase + (uint32_t)(s % 3) * (GBUF * 4);
        const int kof = s * 64 + lseg * 8;
        #pragma unroll
        for (int i = 0; i < 8; i++) {           // A: 256 rows x 8 segs / 256 thr
            const int row = lrow + i * 32;
            CP_ASYNC16(base + (uint32_t)((row * GSTR + lseg * 4) * 4),
                       Ag + (size_t)row * DIM + kof);
        }
        #pragma unroll
        for (int i = 0; i < 4; i++) {           // B: 128 rows x 8 segs / 256 thr
            const int row = lrow + i * 32;
            CP_ASYNC16(base + (uint32_t)((GSTAGE_A + row * GSTR + lseg * 4) * 4),
                       Bg + (size_t)row * DIM + kof);
        }
        CP_COMMIT();
    };

    float c[4][8][4];
    #pragma unroll
    for (int i = 0; i < 4; i++)
        #pragma unroll
        for (int j = 0; j < 8; j++)
            #pragma unroll
            for (int k = 0; k < 4; k++)
                c[i][j][k] = 0.0f;

    prefetch(0);
    prefetch(1);

    const int NS = DIM / 64;   // 16 stages
    for (int s = 0; s < NS; s++) {
        if (s + 1 < NS) { CP_WAIT1(); } else { CP_WAIT0(); }
        __syncthreads();
        // Buffer (s+2)%3 == (s-1)%3: fully consumed before the barrier above.
        if (s + 2 < NS) prefetch(s + 2);

        const uint32_t* Au = smw + (s % 3) * GBUF;
        const uint32_t* Bu = Au + GSTAGE_A;

        #pragma unroll
        for (int kt = 0; kt < 4; kt++) {
            uint32_t af[4][4], bf[8][2];
            const int ko = kt * 8 + tig;
            #pragma unroll
            for (int am = 0; am < 4; am++) {
                const uint32_t* p = Au + (wm * 64 + am * 16 + gid) * GSTR + ko;
                af[am][0] = p[0];
                af[am][1] = p[8 * GSTR];
                af[am][2] = p[4];
                af[am][3] = p[8 * GSTR + 4];
            }
            #pragma unroll
            for (int bn = 0; bn < 8; bn++) {
                const uint32_t* p = Bu + (wn * 64 + bn * 8 + gid) * GSTR + ko;
                bf[bn][0] = p[0];
                bf[bn][1] = p[4];
            }
            #pragma unroll
            for (int am = 0; am < 4; am++)
                #pragma unroll
                for (int bn = 0; bn < 8; bn++)
                    MMA_F16(c[am][bn], af[am], bf[bn][0], bf[bn][1]);
        }
    }

    const int rbase = by * 256 + wm * 64 + gid;
    const int cbase = bx * 128 + wn * 64 + tig * 2;
    #pragma unroll
    for (int am = 0; am < 4; am++) {
        #pragma unroll
        for (int bn = 0; bn < 8; bn++) {
            const int col = cbase + bn * 8;
            const int r0  = rbase + am * 16;
            const float v00 = c[am][bn][0], v01 = c[am][bn][1];
            const float v10 = c[am][bn][2], v11 = c[am][bn][3];
            if (mode == 0) {
                float b0 = bias[col], b1 = bias[col + 1];
                *reinterpret_cast<float2*>(Cf + (size_t)r0 * DIM + col) =
                    make_float2(v00 + b0, v01 + b1);
                *reinterpret_cast<float2*>(Cf + (size_t)(r0 + 8) * DIM + col) =
                    make_float2(v10 + b0, v11 + b1);
            } else if (mode == 1) {
                reinterpret_cast<uint32_t*>(Ch)[((size_t)r0 * DIM + col) >> 1] =
                    h2bits(__floats2half2_rn(v00 * 0.125f, v01 * 0.125f));
                reinterpret_cast<uint32_t*>(Ch)[((size_t)(r0 + 8) * DIM + col) >> 1] =
                    h2bits(__floats2half2_rn(v10 * 0.125f, v11 * 0.125f));
            } else if (mode == 2) {
                reinterpret_cast<uint32_t*>(Ch)[((size_t)r0 * DIM + col) >> 1] =
                    h2bits(__floats2half2_rn(v00, v01));
                reinterpret_cast<uint32_t*>(Ch)[((size_t)(r0 + 8) * DIM + col) >> 1] =
                    h2bits(__floats2half2_rn(v10, v11));
            } else {
                const size_t bb = (size_t)(r0 >> 11) * 2097152;
                const int s0 = r0 & 2047;
                Ch[bb + (size_t)col * 2048 + s0]           = __float2half_rn(v00);
                Ch[bb + (size_t)(col + 1) * 2048 + s0]     = __float2half_rn(v01);
                Ch[bb + (size_t)col * 2048 + s0 + 8]       = __float2half_rn(v10);
                Ch[bb + (size_t)(col + 1) * 2048 + s0 + 8] = __float2half_rn(v11);
            }
        }
    }
}

// ---------------------------------------------------------------------------
// Tensor-core flash attention (R15 proven): 1-term fp16 QK + fp16 PV.
// Pure-copy tiles, 128 thr = 4 warps, 64 q rows, kv tiles of 64.
// ---------------------------------------------------------------------------
#define ATTN_SMEM (3*64*36*4)    // 27648 B

__global__ __launch_bounds__(128, 4) void attn_tc_kernel(
    const __half* __restrict__ Qh, const __half* __restrict__ Kh,
    const __half* __restrict__ Vt, __half* __restrict__ Oout)
{
    extern __shared__ uint32_t smw[];
    uint32_t* PpW = smw;
    uint32_t* KhU = smw + 64 * 36;
    uint32_t* VpW = KhU + 64 * 36;

    const int b    = blockIdx.z;
    const int h    = blockIdx.y;
    const int q0   = (gridDim.x - 1 - blockIdx.x) * 64;
    const int tid  = threadIdx.x;
    const int wq   = tid >> 5;
    const int lane = tid & 31;
    const int gid  = lane >> 2;
    const int tig  = lane & 3;

    const __half* Qg  = Qh + ((size_t)b * SEQ + q0) * DIM + h * HD;
    const __half* Khg = Kh + (size_t)b * SEQ * DIM + h * HD;
    const __half* Vtg = Vt + (size_t)(b * NH + h) * (HD * SEQ);

    #pragma unroll
    for (int i = 0; i < 4; i++) {
        int idx = tid + i * 128;
        int r = idx >> 3, seg = idx & 7;
        *reinterpret_cast<uint4*>(PpW + r * 36 + seg * 4) =
            *reinterpret_cast<const uint4*>(Qg + (size_t)r * DIM + seg * 8);
    }
    __syncthreads();

    uint32_t qh[4][4];
    {
        const int rr = wq * 16 + gid;
        #pragma unroll
        for (int kt = 0; kt < 4; kt++) {
            qh[kt][0] = PpW[rr * 36 + kt * 8 + tig];
            qh[kt][1] = PpW[(rr + 8) * 36 + kt * 8 + tig];
            qh[kt][2] = PpW[rr * 36 + kt * 8 + 4 + tig];
            qh[kt][3] = PpW[(rr + 8) * 36 + kt * 8 + 4 + tig];
        }
    }

    float m0 = -1e30f, m1 = -1e30f, l0 = 0.0f, l1 = 0.0f;
    float o[8][4];
    #pragma unroll
    for (int nt = 0; nt < 8; nt++)
        #pragma unroll
        for (int e = 0; e < 4; e++) o[nt][e] = 0.0f;

    const int ntiles = (q0 >> 6) + 1;
    for (int t = 0; t < ntiles; t++) {
        const int kv0 = t * 64;
        __syncthreads();
        #pragma unroll
        for (int i = 0; i < 4; i++) {
            int idx = tid + i * 128;
            int r = idx >> 3, seg = idx & 7;
            *reinterpret_cast<uint4*>(KhU + r * 36 + seg * 4) =
                *reinterpret_cast<const uint4*>(Khg + (size_t)(kv0 + r) * DIM + seg * 8);
            *reinterpret_cast<uint4*>(VpW + r * 36 + seg * 4) =
                *reinterpret_cast<const uint4*>(Vtg + (size_t)r * SEQ + kv0 + seg * 8);
        }
        __syncthreads();

        float s[8][4];
        #pragma unroll
        for (int nt = 0; nt < 8; nt++)
            #pragma unroll
            for (int e = 0; e < 4; e++) s[nt][e] = 0.0f;

        #pragma unroll
        for (int kt = 0; kt < 4; kt++) {
            #pragma unroll
            for (int nt = 0; nt < 8; nt++) {
                const int boff = (nt * 8 + gid) * 36 + kt * 8 + tig;
                MMA_F16(s[nt], qh[kt], KhU[boff], KhU[boff + 4]);
            }
        }

        const int r0g = q0 + wq * 16 + gid;
        const int r1g = r0g + 8;
        if (kv0 == q0) {
            #pragma unroll
            for (int nt = 0; nt < 8; nt++) {
                const int c0 = kv0 + nt * 8 + 2 * tig;
                if (c0     > r0g) s[nt][0] = -1e30f;
                if (c0 + 1 > r0g) s[nt][1] = -1e30f;
                if (c0     > r1g) s[nt][2] = -1e30f;
                if (c0 + 1 > r1g) s[nt][3] = -1e30f;
            }
        }

        float mx0 = -1e30f, mx1 = -1e30f;
        #pragma unroll
        for (int nt = 0; nt < 8; nt++) {
            mx0 = fmaxf(mx0, fmaxf(s[nt][0], s[nt][1]));
            mx1 = fmaxf(mx1, fmaxf(s[nt][2], s[nt][3]));
        }
        mx0 = fmaxf(mx0, __shfl_xor_sync(0xffffffffu, mx0, 1));
        mx0 = fmaxf(mx0, __shfl_xor_sync(0xffffffffu, mx0, 2));
        mx1 = fmaxf(mx1, __shfl_xor_sync(0xffffffffu, mx1, 1));
        mx1 = fmaxf(mx1, __shfl_xor_sync(0xffffffffu, mx1, 2));

        const float nm0 = fmaxf(m0, mx0);
        const float nm1 = fmaxf(m1, mx1);
        const float sc0 = __expf(m0 - nm0);
        const float sc1 = __expf(m1 - nm1);
        m0 = nm0; m1 = nm1;
        l0 *= sc0; l1 *= sc1;

        float sum0 = 0.0f, sum1 = 0.0f;
        const int prow = wq * 16 + gid;
        #pragma unroll
        for (int nt = 0; nt < 8; nt++) {
            float p00 = __expf(s[nt][0] - m0);
            float p01 = __expf(s[nt][1] - m0);
            float p10 = __expf(s[nt][2] - m1);
            float p11 = __expf(s[nt][3] - m1);
            sum0 += p00 + p01;
            sum1 += p10 + p11;
            PpW[prow * 36 + nt * 4 + tig]       = h2bits(__floats2half2_rn(p00, p01));
            PpW[(prow + 8) * 36 + nt * 4 + tig] = h2bits(__floats2half2_rn(p10, p11));
            o[nt][0] *= sc0; o[nt][1] *= sc0;
            o[nt][2] *= sc1; o[nt][3] *= sc1;
        }
        sum0 += __shfl_xor_sync(0xffffffffu, sum0, 1);
        sum0 += __shfl_xor_sync(0xffffffffu, sum0, 2);
        sum1 += __shfl_xor_sync(0xffffffffu, sum1, 1);
        sum1 += __shfl_xor_sync(0xffffffffu, sum1, 2);
        l0 += sum0; l1 += sum1;

        __syncwarp();

        #pragma unroll
        for (int kt = 0; kt < 4; kt++) {
            uint32_t a[4];
            a[0] = PpW[prow * 36 + kt * 8 + tig];
            a[1] = PpW[(prow + 8) * 36 + kt * 8 + tig];
            a[2] = PpW[prow * 36 + kt * 8 + 4 + tig];
            a[3] = PpW[(prow + 8) * 36 + kt * 8 + 4 + tig];
            #pragma unroll
            for (int nt = 0; nt < 8; nt++) {
                const int voff = (nt * 8 + gid) * 36 + kt * 8 + tig;
                MMA_F16(o[nt], a, VpW[voff], VpW[voff + 4]);
            }
        }
        __syncwarp();
    }

    const float inv0 = 1.0f / l0;
    const float inv1 = 1.0f / l1;
    const int r0g = q0 + wq * 16 + gid;
    uint32_t* OgW = reinterpret_cast<uint32_t*>(
        Oout + (size_t)b * SEQ * DIM + h * HD);
    #pragma unroll
    for (int nt = 0; nt < 8; nt++) {
        const int col = nt * 8 + 2 * tig;
        OgW[((size_t)r0g * DIM + col) >> 1] =
            h2bits(__floats2half2_rn(o[nt][0] * inv0, o[nt][1] * inv0));
        OgW[((size_t)(r0g + 8) * DIM + col) >> 1] =
            h2bits(__floats2half2_rn(o[nt][2] * inv1, o[nt][3] * inv1));
    }
}

// ---------------------------------------------------------------------------
// Launch
// ---------------------------------------------------------------------------
extern "C" void kernel_launch(void* const* d_in, const int* in_sizes, int n_in,
                              void* d_out, int out_size)
{
    const float* x  = (const float*)d_in[0];
    const float* Wq = (const float*)d_in[1];
    const float* Wk = (const float*)d_in[2];
    const float* Wv = (const float*)d_in[3];
    const float* Wo = (const float*)d_in[4];
    const float* bo = (const float*)d_in[5];
    float* out = (float*)d_out;

    __half *xh, *ah, *qh, *kh, *vt, *wqt, *wkt, *wvt, *wot;
    cudaGetSymbolAddress((void**)&xh,  g_xh);
    cudaGetSymbolAddress((void**)&ah,  g_ah);
    cudaGetSymbolAddress((void**)&qh,  g_qh);
    cudaGetSymbolAddress((void**)&kh,  g_kh);
    cudaGetSymbolAddress((void**)&vt,  g_vt);
    cudaGetSymbolAddress((void**)&wqt, g_wqt);
    cudaGetSymbolAddress((void**)&wkt, g_wkt);
    cudaGetSymbolAddress((void**)&wvt, g_wvt);
    cudaGetSymbolAddress((void**)&wot, g_wot);

    cudaFuncSetAttribute(gemm_f16_kernel,
                         cudaFuncAttributeMaxDynamicSharedMemorySize, GEMM_SMEM);
    cudaFuncSetAttribute(attn_tc_kernel,
                         cudaFuncAttributeMaxDynamicSharedMemorySize, ATTN_SMEM);

    // 1) fused prep: 4 weight transposes + x -> fp16, one launch
    Ptr4 tp;
    tp.W[0] = Wq;   tp.W[1] = Wk;   tp.W[2] = Wv;   tp.W[3] = Wo;
    tp.WT[0] = wqt; tp.WT[1] = wkt; tp.WT[2] = wvt; tp.WT[3] = wot;
    dim3 prep_grid(DIM / 32, DIM / 32, 5);
    prep_kernel<<<prep_grid, 256>>>(tp, x, xh);

    // 2) Q/K/V projections — 128 CTAs = one full wave each
    dim3 gemm_grid(DIM / 128, MTOT / 256);
    gemm_f16_kernel<<<gemm_grid, 256, GEMM_SMEM>>>(xh, wqt, nullptr, qh, nullptr, 1);
    gemm_f16_kernel<<<gemm_grid, 256, GEMM_SMEM>>>(xh, wkt, nullptr, kh, nullptr, 2);
    gemm_f16_kernel<<<gemm_grid, 256, GEMM_SMEM>>>(xh, wvt, nullptr, vt, nullptr, 3);

    // 3) attention (1-term fp16 QK, fp16 PV, fp16 output)
    dim3 attn_grid(SEQ / 64, NH, BATCH);     // (32, 16, 2)
    attn_tc_kernel<<<attn_grid, 128, ATTN_SMEM>>>(qh, kh, vt, ah);

    // 4) output projection (+bias, fp32 out)
    gemm_f16_kernel<<<gemm_grid, 256, GEMM_SMEM>>>(ah, wot, out, nullptr, bo, 0);
}